// round 8
// baseline (speedup 1.0000x reference)
#include <cuda_runtime.h>
#include <cuda_fp16.h>
#include <math.h>
#include <stdint.h>

#define BATCH 4
#define SEQ   2048
#define DMODEL 1024
#define NHEADS 16
#define DK    64
#define DFF   4096
#define NTOK  (BATCH*SEQ)          // 8192
#define QKV_STR 3072

// ---------------- scratch (device globals; no allocation allowed) ----------
__device__ __half g_h   [NTOK*DMODEL];
__device__ __half g_qkv [NTOK*QKV_STR];
__device__ __half g_att [NTOK*DMODEL];
__device__ float  g_x1  [NTOK*DMODEL];
__device__ __half g_h2  [NTOK*DMODEL];
__device__ __half g_ff1 [NTOK*DFF];
// transposed (K-major, fp16) weights
__device__ __half g_wqkvt[3*DMODEL*DMODEL];  // [N=3072, K=1024]
__device__ float  g_bqkv [QKV_STR];
__device__ __half g_wot[DMODEL*DMODEL];
__device__ __half g_w1t[DFF*DMODEL];
__device__ __half g_w2t[DMODEL*DFF];

// ---------------- helpers ----------------------------------------------------
__device__ __forceinline__ uint32_t smem_u32(const void* p) {
    uint32_t a;
    asm("{ .reg .u64 t; cvta.to.shared.u64 t, %1; cvt.u32.u64 %0, t; }"
        : "=r"(a) : "l"(p));
    return a;
}
__device__ __forceinline__ void cp_async16(uint32_t dst, const void* src) {
    asm volatile("cp.async.cg.shared.global [%0], [%1], 16;" :: "r"(dst), "l"(src));
}

__device__ __forceinline__ void mma_f16(float (&d)[4], const uint32_t (&a)[4],
                                        const uint32_t (&b)[2]) {
    asm volatile("mma.sync.aligned.m16n8k16.row.col.f32.f16.f16.f32 "
        "{%0,%1,%2,%3}, {%4,%5,%6,%7}, {%8,%9}, {%0,%1,%2,%3};"
        : "+f"(d[0]), "+f"(d[1]), "+f"(d[2]), "+f"(d[3])
        : "r"(a[0]), "r"(a[1]), "r"(a[2]), "r"(a[3]), "r"(b[0]), "r"(b[1]));
}
__device__ __forceinline__ void ldmx4(uint32_t (&r)[4], uint32_t addr) {
    asm volatile("ldmatrix.sync.aligned.m8n8.x4.shared.b16 {%0,%1,%2,%3}, [%4];"
        : "=r"(r[0]), "=r"(r[1]), "=r"(r[2]), "=r"(r[3]) : "r"(addr));
}
__device__ __forceinline__ void ldmx4t(uint32_t (&r)[4], uint32_t addr) {
    asm volatile("ldmatrix.sync.aligned.m8n8.x4.trans.shared.b16 "
        "{%0,%1,%2,%3}, [%4];"
        : "=r"(r[0]), "=r"(r[1]), "=r"(r[2]), "=r"(r[3]) : "r"(addr));
}

// ---------------- layernorm: one block per token row -> fp16 out ------------
__global__ __launch_bounds__(256) void ln_kernel(const float* __restrict__ x,
                                                 const float* __restrict__ g,
                                                 const float* __restrict__ b,
                                                 __half* __restrict__ y)
{
    const int row = blockIdx.x;
    const int tid = threadIdx.x;
    const float* xr = x + (size_t)row * DMODEL;
    float4 v = *(const float4*)(xr + tid * 4);
    float s  = v.x + v.y + v.z + v.w;
    float s2 = v.x*v.x + v.y*v.y + v.z*v.z + v.w*v.w;

    __shared__ float red[64], red2[64];
    for (int o = 16; o > 0; o >>= 1) {
        s  += __shfl_xor_sync(0xffffffffu, s,  o);
        s2 += __shfl_xor_sync(0xffffffffu, s2, o);
    }
    int wid = tid >> 5, lid = tid & 31;
    if (lid == 0) { red[wid] = s; red2[wid] = s2; }
    __syncthreads();
    if (wid == 0) {
        float a  = (lid < 8) ? red[lid]  : 0.f;
        float a2 = (lid < 8) ? red2[lid] : 0.f;
        for (int o = 4; o > 0; o >>= 1) {
            a  += __shfl_xor_sync(0xffffffffu, a,  o);
            a2 += __shfl_xor_sync(0xffffffffu, a2, o);
        }
        if (lid == 0) { red[0] = a; red2[0] = a2; }
    }
    __syncthreads();
    float mu  = red[0]  * (1.0f / DMODEL);
    float var = red2[0] * (1.0f / DMODEL) - mu * mu;
    float rstd = rsqrtf(var + 1e-5f);

    int c = tid * 4;
    float4 gg = *(const float4*)(g + c);
    float4 bb = *(const float4*)(b + c);
    __half2 h01 = __floats2half2_rn((v.x - mu) * rstd * gg.x + bb.x,
                                    (v.y - mu) * rstd * gg.y + bb.y);
    __half2 h23 = __floats2half2_rn((v.z - mu) * rstd * gg.z + bb.z,
                                    (v.w - mu) * rstd * gg.w + bb.w);
    uint2 u;
    u.x = *(uint32_t*)&h01; u.y = *(uint32_t*)&h23;
    *(uint2*)(y + (size_t)row * DMODEL + c) = u;
}

// ---------------- weight transpose -> fp16: Wt[n,k] = h(W[k,n]) -------------
__global__ __launch_bounds__(256) void tp_h(const float* __restrict__ W,
                                            __half* __restrict__ Wt, int K, int N)
{
    __shared__ float t[32][33];
    int n0 = blockIdx.x * 32, k0 = blockIdx.y * 32;
    int tx = threadIdx.x, ty = threadIdx.y;  // 32 x 8
#pragma unroll
    for (int i = 0; i < 4; i++)
        t[ty + i*8][tx] = W[(size_t)(k0 + ty + i*8) * N + n0 + tx];
    __syncthreads();
#pragma unroll
    for (int i = 0; i < 4; i++)
        Wt[(size_t)(n0 + ty + i*8) * K + k0 + tx] = __float2half_rn(t[tx][ty + i*8]);
}

__global__ void bias_cat(const float* bq, const float* bk, const float* bv,
                         float* o)
{
    int i = blockIdx.x * 256 + threadIdx.x;
    o[i] = (i < DMODEL) ? bq[i] : (i < 2*DMODEL) ? bk[i - DMODEL] : bv[i - 2*DMODEL];
}

// ---------------- fp16 mma.sync GEMM: C = A[M,K] @ Bt[N,K]^T + epilogue -----
// 128x128 tile, BK=64, 256 threads (8 warps, warp tile 64x32), 2-stage cp.async.
// All fragments via ldmatrix.x4 (stride-72 rows are conflict-free).
// EPI: 0 = bias -> half, 1 = bias+gelu -> half, 2 = bias+residual -> float
#define GST 72
#define GSTAGE_H (128*GST)     // halves per stage per operand

template<int EPI, typename TC>
__global__ __launch_bounds__(256, 2)
void gemm_mma(const __half* __restrict__ A, const __half* __restrict__ Bt,
              const float* __restrict__ bias, const float* __restrict__ res,
              TC* __restrict__ C, int M, int N, int K)
{
    extern __shared__ __half smh[];
    __half* As = smh;                    // [2][128][GST]
    __half* Bs = smh + 2 * GSTAGE_H;
    const int tid = threadIdx.x, lane = tid & 31, w = tid >> 5;
    const int wm = w & 1, wn = w >> 1;
    const int gid = lane >> 2, tig = lane & 3;
    const int row0 = blockIdx.y * 128, col0 = blockIdx.x * 128;
    const int rlo = (lane & 7) + ((lane >> 3) & 1) * 8;   // ldmatrix row-in-pair
    const int khi = (lane >> 4) * 8;                      // ldmatrix k-half select

    const uint32_t asb = smem_u32(As), bsb = smem_u32(Bs);

    float acc[4][4][4];
#pragma unroll
    for (int i = 0; i < 4; i++)
#pragma unroll
        for (int j = 0; j < 4; j++)
#pragma unroll
            for (int e = 0; e < 4; e++) acc[i][j][e] = 0.f;

    const int NCH = K >> 6;
    {
#pragma unroll
        for (int it = 0; it < 4; it++) {
            int idx = tid + it * 256;      // 0..1023
            int r = idx >> 3, j = idx & 7;
            uint32_t d = (uint32_t)((r * GST + j * 8) * 2);
            cp_async16(asb + d, A  + (size_t)(row0 + r) * K + j * 8);
            cp_async16(bsb + d, Bt + (size_t)(col0 + r) * K + j * 8);
        }
        asm volatile("cp.async.commit_group;" ::: "memory");
    }

    for (int i = 0; i < NCH; i++) {
        const int buf = i & 1;
        if (i + 1 < NCH) {
            const int nb = buf ^ 1;
            const int kof = (i + 1) << 6;
#pragma unroll
            for (int it = 0; it < 4; it++) {
                int idx = tid + it * 256;
                int r = idx >> 3, j = idx & 7;
                uint32_t d = (uint32_t)((nb * GSTAGE_H + r * GST + j * 8) * 2);
                cp_async16(asb + d, A  + (size_t)(row0 + r) * K + kof + j * 8);
                cp_async16(bsb + d, Bt + (size_t)(col0 + r) * K + kof + j * 8);
            }
            asm volatile("cp.async.commit_group;" ::: "memory");
            asm volatile("cp.async.wait_group 1;" ::: "memory");
        } else {
            asm volatile("cp.async.wait_group 0;" ::: "memory");
        }
        __syncthreads();

        const uint32_t ab = asb + (uint32_t)(buf * GSTAGE_H * 2);
        const uint32_t bb = bsb + (uint32_t)(buf * GSTAGE_H * 2);
#pragma unroll
        for (int ks = 0; ks < 4; ks++) {
            const int kb = ks * 16 + khi;
            uint32_t af[4][4], bq[2][4];
#pragma unroll
            for (int mt = 0; mt < 4; mt++)
                ldmx4(af[mt], ab + (uint32_t)(((wm * 64 + mt * 16 + rlo) * GST + kb) * 2));
#pragma unroll
            for (int np = 0; np < 2; np++)
                ldmx4(bq[np], bb + (uint32_t)(((wn * 32 + np * 16 + rlo) * GST + kb) * 2));
#pragma unroll
            for (int mt = 0; mt < 4; mt++)
#pragma unroll
                for (int np = 0; np < 2; np++) {
                    uint32_t b0[2] = {bq[np][0], bq[np][2]};
                    uint32_t b1[2] = {bq[np][1], bq[np][3]};
                    mma_f16(acc[mt][np * 2],     af[mt], b0);
                    mma_f16(acc[mt][np * 2 + 1], af[mt], b1);
                }
        }
        __syncthreads();
    }

#pragma unroll
    for (int mt = 0; mt < 4; mt++) {
        const int r0 = row0 + wm * 64 + mt * 16 + gid;
#pragma unroll
        for (int nt = 0; nt < 4; nt++) {
            const int c = col0 + wn * 32 + nt * 8 + 2 * tig;
            const float b0 = bias[c], b1 = bias[c + 1];
            float o00 = acc[mt][nt][0] + b0, o01 = acc[mt][nt][1] + b1;
            float o10 = acc[mt][nt][2] + b0, o11 = acc[mt][nt][3] + b1;
            if (EPI == 1) {
                o00 = 0.5f * o00 * (1.0f + erff(o00 * 0.70710678118654752f));
                o01 = 0.5f * o01 * (1.0f + erff(o01 * 0.70710678118654752f));
                o10 = 0.5f * o10 * (1.0f + erff(o10 * 0.70710678118654752f));
                o11 = 0.5f * o11 * (1.0f + erff(o11 * 0.70710678118654752f));
            } else if (EPI == 2) {
                const float* rp0 = res + (size_t)r0 * N + c;
                const float* rp1 = res + (size_t)(r0 + 8) * N + c;
                o00 += rp0[0]; o01 += rp0[1];
                o10 += rp1[0]; o11 += rp1[1];
            }
            if (EPI == 2) {
                *(float2*)((float*)C + (size_t)r0 * N + c)       = make_float2(o00, o01);
                *(float2*)((float*)C + (size_t)(r0 + 8) * N + c) = make_float2(o10, o11);
            } else {
                __half2 v0 = __floats2half2_rn(o00, o01);
                __half2 v1 = __floats2half2_rn(o10, o11);
                *(uint32_t*)((__half*)C + (size_t)r0 * N + c)       = *(uint32_t*)&v0;
                *(uint32_t*)((__half*)C + (size_t)(r0 + 8) * N + c) = *(uint32_t*)&v1;
            }
        }
    }
}

// ---------------- attention: fp16 mma.sync flash-style ----------------------
// block = (b,h) x 128 q-rows; 256 threads = 8 warps x 16 q-rows.
// K/V 64-token tiles double-buffered; P stays in registers (S C-frag == P A-frag).
#define APAD 72
#define KS_H (64*APAD)          // halves
#define VS_H (64*APAD)
#define KS_B (KS_H*2)
#define VS_B (VS_H*2)
#define ATT_SMEM ((2*KS_H + 2*VS_H)*2 + 2*64*4)   // 37376 B

__global__ __launch_bounds__(256, 2)
void attn_mma(const __half* __restrict__ QKV, const int* __restrict__ mask,
              __half* __restrict__ O)
{
    extern __shared__ __half sm[];
    __half* Ks = sm;
    __half* Vs = sm + 2 * KS_H;
    int*    Ms = (int*)(Vs + 2 * VS_H);

    const int tid = threadIdx.x, lane = tid & 31, w = tid >> 5;
    const int gid = lane >> 2, tig = lane & 3;
    const int b = blockIdx.y >> 4, h = blockIdx.y & 15;
    const int q0 = blockIdx.x * 128, m0 = w * 16;
    const size_t tokbase = (size_t)b * SEQ;
    const int qoff = h * DK, koff = DMODEL + h * DK, voff = 2 * DMODEL + h * DK;
    const int rlo = (lane & 7) + ((lane >> 3) & 1) * 8;
    const int khi = (lane >> 4) * 8;

    const uint32_t ksb = smem_u32(Ks), vsb = smem_u32(Vs), msb = smem_u32(Ms);

    // ---- stage Q (scaled by 1/8) into Ks(rows 0-63)/Vs(rows 64-127) --------
    const __half2 qscale = __floats2half2_rn(0.125f, 0.125f);
#pragma unroll
    for (int it = 0; it < 4; it++) {
        int idx = tid + it * 256;             // 0..1023 chunks of 8 halves
        int r = idx >> 3, j = (idx & 7) * 8;
        uint4 t = *(const uint4*)(QKV + (tokbase + q0 + r) * QKV_STR + qoff + j);
        __half2* hp = (__half2*)&t;
#pragma unroll
        for (int e = 0; e < 4; e++) hp[e] = __hmul2(hp[e], qscale);
        __half* dst = (r < 64) ? (Ks + r * APAD + j) : (Vs + (r - 64) * APAD + j);
        *(uint4*)dst = t;
    }
    __syncthreads();
    uint32_t qf[4][4];
    {
        const uint32_t qbase = (m0 < 64) ? ksb : vsb;
        const int qrow = (m0 < 64) ? m0 : m0 - 64;
#pragma unroll
        for (int ks = 0; ks < 4; ks++)
            ldmx4(qf[ks], qbase + (uint32_t)(((qrow + rlo) * APAD + ks * 16 + khi) * 2));
    }
    __syncthreads();

    float o[8][4];
#pragma unroll
    for (int a = 0; a < 8; a++)
#pragma unroll
        for (int e = 0; e < 4; e++) o[a][e] = 0.f;
    float l0 = 0.f, l1 = 0.f;

    // prologue: load tile 0 into buf 0
    {
#pragma unroll
        for (int it = 0; it < 2; it++) {
            int idx = tid + it * 256;        // 0..511
            int r = idx >> 3, j = (idx & 7) * 8;
            const __half* src = QKV + (tokbase + r) * QKV_STR;
            cp_async16(ksb + (uint32_t)((r * APAD + j) * 2), src + koff + j);
            cp_async16(vsb + (uint32_t)((r * APAD + j) * 2), src + voff + j);
        }
        if (tid < 16) cp_async16(msb + tid * 16, mask + b * SEQ + tid * 4);
        asm volatile("cp.async.commit_group;" ::: "memory");
    }

    const int NT = SEQ / 64;
    for (int kt = 0; kt < NT; kt++) {
        const int buf = kt & 1;
        if (kt + 1 < NT) {
            const int nb = buf ^ 1;
            const int t0 = (kt + 1) * 64;
#pragma unroll
            for (int it = 0; it < 2; it++) {
                int idx = tid + it * 256;
                int r = idx >> 3, j = (idx & 7) * 8;
                const __half* src = QKV + (tokbase + t0 + r) * QKV_STR;
                cp_async16(ksb + (uint32_t)((nb * KS_H + r * APAD + j) * 2), src + koff + j);
                cp_async16(vsb + (uint32_t)((nb * VS_H + r * APAD + j) * 2), src + voff + j);
            }
            if (tid < 16) cp_async16(msb + nb * 256 + tid * 16, mask + b * SEQ + t0 + tid * 4);
            asm volatile("cp.async.commit_group;" ::: "memory");
            asm volatile("cp.async.wait_group 1;" ::: "memory");
        } else {
            asm volatile("cp.async.wait_group 0;" ::: "memory");
        }
        __syncthreads();

        const uint32_t kb_ = ksb + (uint32_t)(buf * KS_B);
        const uint32_t vb_ = vsb + (uint32_t)(buf * VS_B);
        const int*     ms_ = Ms + buf * 64;

#pragma unroll
        for (int atp = 0; atp < 4; atp++) {
            const int n0 = atp * 16;
            float s0[4] = {0.f, 0.f, 0.f, 0.f};
            float s1[4] = {0.f, 0.f, 0.f, 0.f};
#pragma unroll
            for (int ks = 0; ks < 4; ks++) {
                uint32_t kf[4];
                ldmx4(kf, kb_ + (uint32_t)(((n0 + rlo) * APAD + ks * 16 + khi) * 2));
                uint32_t b0[2] = {kf[0], kf[2]};
                uint32_t b1[2] = {kf[1], kf[3]};
                mma_f16(s0, qf[ks], b0);
                mma_f16(s1, qf[ks], b1);
            }
            const int c0 = n0 + 2 * tig;
            const int mk0 = ms_[c0],     mk1 = ms_[c0 + 1];
            const int mk2 = ms_[c0 + 8], mk3 = ms_[c0 + 9];
            float p00 = mk0 ? __expf(s0[0]) : 0.f;
            float p01 = mk1 ? __expf(s0[1]) : 0.f;
            float p02 = mk0 ? __expf(s0[2]) : 0.f;
            float p03 = mk1 ? __expf(s0[3]) : 0.f;
            float p10 = mk2 ? __expf(s1[0]) : 0.f;
            float p11 = mk3 ? __expf(s1[1]) : 0.f;
            float p12 = mk2 ? __expf(s1[2]) : 0.f;
            float p13 = mk3 ? __expf(s1[3]) : 0.f;
            l0 += p00 + p01 + p10 + p11;
            l1 += p02 + p03 + p12 + p13;
            uint32_t af[4];
            __half2 t;
            t = __floats2half2_rn(p00, p01); af[0] = *(uint32_t*)&t;
            t = __floats2half2_rn(p02, p03); af[1] = *(uint32_t*)&t;
            t = __floats2half2_rn(p10, p11); af[2] = *(uint32_t*)&t;
            t = __floats2half2_rn(p12, p13); af[3] = *(uint32_t*)&t;
#pragma unroll
            for (int dp = 0; dp < 4; dp++) {
                uint32_t vf[4];
                ldmx4t(vf, vb_ + (uint32_t)(((n0 + rlo) * APAD + dp * 16 + khi) * 2));
                uint32_t b0[2] = {vf[0], vf[1]};
                uint32_t b1[2] = {vf[2], vf[3]};
                mma_f16(o[2 * dp],     af, b0);
                mma_f16(o[2 * dp + 1], af, b1);
            }
        }
        __syncthreads();   // all warps done with this buf before it is reloaded
    }

    // row sums across quad
    l0 += __shfl_xor_sync(0xffffffffu, l0, 1);
    l0 += __shfl_xor_sync(0xffffffffu, l0, 2);
    l1 += __shfl_xor_sync(0xffffffffu, l1, 1);
    l1 += __shfl_xor_sync(0xffffffffu, l1, 2);
    const float inv0 = 1.0f / l0, inv1 = 1.0f / l1;

    __half* o0 = O + (tokbase + q0 + m0 + gid)     * DMODEL + h * DK;
    __half* o1 = O + (tokbase + q0 + m0 + gid + 8) * DMODEL + h * DK;
#pragma unroll
    for (int at = 0; at < 8; at++) {
        const int c = at * 8 + 2 * tig;
        __half2 v0 = __floats2half2_rn(o[at][0] * inv0, o[at][1] * inv0);
        __half2 v1 = __floats2half2_rn(o[at][2] * inv1, o[at][3] * inv1);
        *(uint32_t*)(o0 + c) = *(uint32_t*)&v0;
        *(uint32_t*)(o1 + c) = *(uint32_t*)&v1;
    }
}

// ---------------- launcher ---------------------------------------------------
extern "C" void kernel_launch(void* const* d_in, const int* in_sizes, int n_in,
                              void* d_out, int out_size)
{
    const float* x     = (const float*)d_in[0];
    const int*   mask  = (const int*)  d_in[1];
    const float* Wq    = (const float*)d_in[2];
    const float* bq    = (const float*)d_in[3];
    const float* Wk    = (const float*)d_in[4];
    const float* bk    = (const float*)d_in[5];
    const float* Wv    = (const float*)d_in[6];
    const float* bv    = (const float*)d_in[7];
    const float* Wo    = (const float*)d_in[8];
    const float* bo    = (const float*)d_in[9];
    const float* W1    = (const float*)d_in[10];
    const float* b1    = (const float*)d_in[11];
    const float* W2    = (const float*)d_in[12];
    const float* b2    = (const float*)d_in[13];
    const float* ln1g  = (const float*)d_in[14];
    const float* ln1b  = (const float*)d_in[15];
    const float* ln2g  = (const float*)d_in[16];
    const float* ln2b  = (const float*)d_in[17];
    float* out = (float*)d_out;

    __half *h, *qkv, *att, *h2, *ff1, *wqkvt, *wot, *w1t, *w2t;
    float *x1, *bqkv;
    cudaGetSymbolAddress((void**)&h,    g_h);
    cudaGetSymbolAddress((void**)&qkv,  g_qkv);
    cudaGetSymbolAddress((void**)&att,  g_att);
    cudaGetSymbolAddress((void**)&x1,   g_x1);
    cudaGetSymbolAddress((void**)&h2,   g_h2);
    cudaGetSymbolAddress((void**)&ff1,  g_ff1);
    cudaGetSymbolAddress((void**)&wqkvt,g_wqkvt);
    cudaGetSymbolAddress((void**)&bqkv, g_bqkv);
    cudaGetSymbolAddress((void**)&wot,  g_wot);
    cudaGetSymbolAddress((void**)&w1t,  g_w1t);
    cudaGetSymbolAddress((void**)&w2t,  g_w2t);

    const int SMEM_GEMM = 4 * GSTAGE_H * 2;   // 73728 B
    cudaFuncSetAttribute((gemm_mma<0, __half>), cudaFuncAttributeMaxDynamicSharedMemorySize, SMEM_GEMM);
    cudaFuncSetAttribute((gemm_mma<1, __half>), cudaFuncAttributeMaxDynamicSharedMemorySize, SMEM_GEMM);
    cudaFuncSetAttribute((gemm_mma<2, float>),  cudaFuncAttributeMaxDynamicSharedMemorySize, SMEM_GEMM);
    cudaFuncSetAttribute(attn_mma, cudaFuncAttributeMaxDynamicSharedMemorySize, ATT_SMEM);

    dim3 tpb(32, 8);
    tp_h<<<dim3(DMODEL/32, DMODEL/32), tpb>>>(Wq, wqkvt,                   DMODEL, DMODEL);
    tp_h<<<dim3(DMODEL/32, DMODEL/32), tpb>>>(Wk, wqkvt + DMODEL*DMODEL,   DMODEL, DMODEL);
    tp_h<<<dim3(DMODEL/32, DMODEL/32), tpb>>>(Wv, wqkvt + 2*DMODEL*DMODEL, DMODEL, DMODEL);
    tp_h<<<dim3(DMODEL/32, DMODEL/32), tpb>>>(Wo, wot, DMODEL, DMODEL);
    tp_h<<<dim3(DFF/32,    DMODEL/32), tpb>>>(W1, w1t, DMODEL, DFF);
    tp_h<<<dim3(DMODEL/32, DFF/32),    tpb>>>(W2, w2t, DFF, DMODEL);
    bias_cat<<<QKV_STR/256, 256>>>(bq, bk, bv, bqkv);

    dim3 gD(DMODEL / 128, NTOK / 128);   // (8, 64)
    dim3 gQKV(QKV_STR / 128, NTOK / 128);// (24, 64)
    dim3 gF(DFF / 128,    NTOK / 128);   // (32, 64)

    // h = LN1(x) -> fp16
    ln_kernel<<<NTOK, 256>>>(x, ln1g, ln1b, h);
    // fused QKV projection -> fp16
    gemm_mma<0, __half><<<gQKV, 256, SMEM_GEMM>>>(h, wqkvt, bqkv, nullptr, qkv, NTOK, QKV_STR, DMODEL);
    // attention -> fp16
    attn_mma<<<dim3(SEQ / 128, BATCH * NHEADS), 256, ATT_SMEM>>>(qkv, mask, att);
    // x1 = x + att @ Wo + bo  (fp32)
    gemm_mma<2, float><<<gD, 256, SMEM_GEMM>>>(att, wot, bo, x, x1, NTOK, DMODEL, DMODEL);
    // h2 = LN2(x1) -> fp16
    ln_kernel<<<NTOK, 256>>>(x1, ln2g, ln2b, h2);
    // ff1 = gelu(h2 @ W1 + b1) -> fp16
    gemm_mma<1, __half><<<gF, 256, SMEM_GEMM>>>(h2, w1t, b1, nullptr, ff1, NTOK, DFF, DMODEL);
    // out = x1 + ff1 @ W2 + b2  (fp32)
    gemm_mma<2, float><<<gD, 256, SMEM_GEMM>>>(ff1, w2t, b2, x1, out, NTOK, DMODEL, DFF);
}

// round 9
// speedup vs baseline: 1.5791x; 1.5791x over previous
#include <cuda_runtime.h>
#include <cuda_fp16.h>
#include <math.h>
#include <stdint.h>

#define BATCH 4
#define SEQ   2048
#define DMODEL 1024
#define NHEADS 16
#define DK    64
#define DFF   4096
#define NTOK  (BATCH*SEQ)          // 8192
#define QKV_STR 3072

// ---------------- scratch (device globals; no allocation allowed) ----------
__device__ __half g_h   [NTOK*DMODEL];
__device__ __half g_qkv [NTOK*QKV_STR];
__device__ __half g_att [NTOK*DMODEL];
__device__ float  g_x1  [NTOK*DMODEL];
__device__ __half g_h2  [NTOK*DMODEL];
__device__ __half g_ff1 [NTOK*DFF];
// transposed (K-major, fp16) weights
__device__ __half g_wqkvt[3*DMODEL*DMODEL];  // [N=3072, K=1024]
__device__ float  g_bqkv [QKV_STR];
__device__ __half g_wot[DMODEL*DMODEL];
__device__ __half g_w1t[DFF*DMODEL];
__device__ __half g_w2t[DMODEL*DFF];

// ---------------- helpers ----------------------------------------------------
__device__ __forceinline__ uint32_t smem_u32(const void* p) {
    uint32_t a;
    asm("{ .reg .u64 t; cvta.to.shared.u64 t, %1; cvt.u32.u64 %0, t; }"
        : "=r"(a) : "l"(p));
    return a;
}
__device__ __forceinline__ void cp_async16(uint32_t dst, const void* src) {
    asm volatile("cp.async.cg.shared.global [%0], [%1], 16;" :: "r"(dst), "l"(src));
}

__device__ __forceinline__ void mma_f16(float (&d)[4], const uint32_t (&a)[4],
                                        const uint32_t (&b)[2]) {
    asm volatile("mma.sync.aligned.m16n8k16.row.col.f32.f16.f16.f32 "
        "{%0,%1,%2,%3}, {%4,%5,%6,%7}, {%8,%9}, {%0,%1,%2,%3};"
        : "+f"(d[0]), "+f"(d[1]), "+f"(d[2]), "+f"(d[3])
        : "r"(a[0]), "r"(a[1]), "r"(a[2]), "r"(a[3]), "r"(b[0]), "r"(b[1]));
}
__device__ __forceinline__ void ldmx4(uint32_t (&r)[4], uint32_t addr) {
    asm volatile("ldmatrix.sync.aligned.m8n8.x4.shared.b16 {%0,%1,%2,%3}, [%4];"
        : "=r"(r[0]), "=r"(r[1]), "=r"(r[2]), "=r"(r[3]) : "r"(addr));
}
__device__ __forceinline__ void ldmx4t(uint32_t (&r)[4], uint32_t addr) {
    asm volatile("ldmatrix.sync.aligned.m8n8.x4.trans.shared.b16 "
        "{%0,%1,%2,%3}, [%4];"
        : "=r"(r[0]), "=r"(r[1]), "=r"(r[2]), "=r"(r[3]) : "r"(addr));
}

// ---------------- layernorm: one block per token row -> fp16 out ------------
__global__ __launch_bounds__(256) void ln_kernel(const float* __restrict__ x,
                                                 const float* __restrict__ g,
                                                 const float* __restrict__ b,
                                                 __half* __restrict__ y)
{
    const int row = blockIdx.x;
    const int tid = threadIdx.x;
    const float* xr = x + (size_t)row * DMODEL;
    float4 v = *(const float4*)(xr + tid * 4);
    float s  = v.x + v.y + v.z + v.w;
    float s2 = v.x*v.x + v.y*v.y + v.z*v.z + v.w*v.w;

    __shared__ float red[64], red2[64];
    for (int o = 16; o > 0; o >>= 1) {
        s  += __shfl_xor_sync(0xffffffffu, s,  o);
        s2 += __shfl_xor_sync(0xffffffffu, s2, o);
    }
    int wid = tid >> 5, lid = tid & 31;
    if (lid == 0) { red[wid] = s; red2[wid] = s2; }
    __syncthreads();
    if (wid == 0) {
        float a  = (lid < 8) ? red[lid]  : 0.f;
        float a2 = (lid < 8) ? red2[lid] : 0.f;
        for (int o = 4; o > 0; o >>= 1) {
            a  += __shfl_xor_sync(0xffffffffu, a,  o);
            a2 += __shfl_xor_sync(0xffffffffu, a2, o);
        }
        if (lid == 0) { red[0] = a; red2[0] = a2; }
    }
    __syncthreads();
    float mu  = red[0]  * (1.0f / DMODEL);
    float var = red2[0] * (1.0f / DMODEL) - mu * mu;
    float rstd = rsqrtf(var + 1e-5f);

    int c = tid * 4;
    float4 gg = *(const float4*)(g + c);
    float4 bb = *(const float4*)(b + c);
    __half2 h01 = __floats2half2_rn((v.x - mu) * rstd * gg.x + bb.x,
                                    (v.y - mu) * rstd * gg.y + bb.y);
    __half2 h23 = __floats2half2_rn((v.z - mu) * rstd * gg.z + bb.z,
                                    (v.w - mu) * rstd * gg.w + bb.w);
    uint2 u;
    u.x = *(uint32_t*)&h01; u.y = *(uint32_t*)&h23;
    *(uint2*)(y + (size_t)row * DMODEL + c) = u;
}

// ---------------- weight transpose -> fp16: Wt[n,k] = h(W[k,n]) -------------
__global__ __launch_bounds__(256) void tp_h(const float* __restrict__ W,
                                            __half* __restrict__ Wt, int K, int N)
{
    __shared__ float t[32][33];
    int n0 = blockIdx.x * 32, k0 = blockIdx.y * 32;
    int tx = threadIdx.x, ty = threadIdx.y;  // 32 x 8
#pragma unroll
    for (int i = 0; i < 4; i++)
        t[ty + i*8][tx] = W[(size_t)(k0 + ty + i*8) * N + n0 + tx];
    __syncthreads();
#pragma unroll
    for (int i = 0; i < 4; i++)
        Wt[(size_t)(n0 + ty + i*8) * K + k0 + tx] = __float2half_rn(t[tx][ty + i*8]);
}

__global__ void bias_cat(const float* bq, const float* bk, const float* bv,
                         float* o)
{
    int i = blockIdx.x * 256 + threadIdx.x;
    o[i] = (i < DMODEL) ? bq[i] : (i < 2*DMODEL) ? bk[i - DMODEL] : bv[i - 2*DMODEL];
}

// ---------------- fp16 mma.sync GEMM (Round-7 scalar-LDS version) -----------
// 128x128 tile, BK=64, 256 threads (8 warps, warp tile 64x32), 2-stage cp.async.
// Smem half tiles stride 72 (conflict-free stores + fragment gathers).
// EPI: 0 = bias -> half, 1 = bias+gelu -> half, 2 = bias+residual -> float
#define GST 72
#define GSTAGE_H (128*GST)     // halves per stage per operand

template<int EPI, typename TC>
__global__ __launch_bounds__(256, 2)
void gemm_mma(const __half* __restrict__ A, const __half* __restrict__ Bt,
              const float* __restrict__ bias, const float* __restrict__ res,
              TC* __restrict__ C, int M, int N, int K)
{
    extern __shared__ __half smh[];
    __half* As = smh;                    // [2][128][GST]
    __half* Bs = smh + 2 * GSTAGE_H;
    const int tid = threadIdx.x, lane = tid & 31, w = tid >> 5;
    const int wm = w & 1, wn = w >> 1;
    const int gid = lane >> 2, tig = lane & 3;
    const int row0 = blockIdx.y * 128, col0 = blockIdx.x * 128;

    const uint32_t asb = smem_u32(As), bsb = smem_u32(Bs);

    float acc[4][4][4];
#pragma unroll
    for (int i = 0; i < 4; i++)
#pragma unroll
        for (int j = 0; j < 4; j++)
#pragma unroll
            for (int e = 0; e < 4; e++) acc[i][j][e] = 0.f;

    const int NCH = K >> 6;
    {
#pragma unroll
        for (int it = 0; it < 4; it++) {
            int idx = tid + it * 256;      // 0..1023
            int r = idx >> 3, j = idx & 7;
            uint32_t d = (uint32_t)((r * GST + j * 8) * 2);
            cp_async16(asb + d, A  + (size_t)(row0 + r) * K + j * 8);
            cp_async16(bsb + d, Bt + (size_t)(col0 + r) * K + j * 8);
        }
        asm volatile("cp.async.commit_group;" ::: "memory");
    }

    for (int i = 0; i < NCH; i++) {
        const int buf = i & 1;
        if (i + 1 < NCH) {
            const int nb = buf ^ 1;
            const int kof = (i + 1) << 6;
#pragma unroll
            for (int it = 0; it < 4; it++) {
                int idx = tid + it * 256;
                int r = idx >> 3, j = idx & 7;
                uint32_t d = (uint32_t)((nb * GSTAGE_H + r * GST + j * 8) * 2);
                cp_async16(asb + d, A  + (size_t)(row0 + r) * K + kof + j * 8);
                cp_async16(bsb + d, Bt + (size_t)(col0 + r) * K + kof + j * 8);
            }
            asm volatile("cp.async.commit_group;" ::: "memory");
            asm volatile("cp.async.wait_group 1;" ::: "memory");
        } else {
            asm volatile("cp.async.wait_group 0;" ::: "memory");
        }
        __syncthreads();

        const __half* as = As + buf * GSTAGE_H;
        const __half* bs = Bs + buf * GSTAGE_H;
#pragma unroll
        for (int ks = 0; ks < 4; ks++) {
            const int k0 = ks * 16 + 2 * tig;
            uint32_t af[4][4], bf[4][2];
#pragma unroll
            for (int mt = 0; mt < 4; mt++) {
                int r = wm * 64 + mt * 16 + gid;
                af[mt][0] = *(const uint32_t*)&as[r * GST + k0];
                af[mt][1] = *(const uint32_t*)&as[(r + 8) * GST + k0];
                af[mt][2] = *(const uint32_t*)&as[r * GST + k0 + 8];
                af[mt][3] = *(const uint32_t*)&as[(r + 8) * GST + k0 + 8];
            }
#pragma unroll
            for (int nt = 0; nt < 4; nt++) {
                int n = wn * 32 + nt * 8 + gid;
                bf[nt][0] = *(const uint32_t*)&bs[n * GST + k0];
                bf[nt][1] = *(const uint32_t*)&bs[n * GST + k0 + 8];
            }
#pragma unroll
            for (int mt = 0; mt < 4; mt++)
#pragma unroll
                for (int nt = 0; nt < 4; nt++)
                    mma_f16(acc[mt][nt], af[mt], bf[nt]);
        }
        __syncthreads();
    }

#pragma unroll
    for (int mt = 0; mt < 4; mt++) {
        const int r0 = row0 + wm * 64 + mt * 16 + gid;
#pragma unroll
        for (int nt = 0; nt < 4; nt++) {
            const int c = col0 + wn * 32 + nt * 8 + 2 * tig;
            const float b0 = bias[c], b1 = bias[c + 1];
            float o00 = acc[mt][nt][0] + b0, o01 = acc[mt][nt][1] + b1;
            float o10 = acc[mt][nt][2] + b0, o11 = acc[mt][nt][3] + b1;
            if (EPI == 1) {
                o00 = 0.5f * o00 * (1.0f + erff(o00 * 0.70710678118654752f));
                o01 = 0.5f * o01 * (1.0f + erff(o01 * 0.70710678118654752f));
                o10 = 0.5f * o10 * (1.0f + erff(o10 * 0.70710678118654752f));
                o11 = 0.5f * o11 * (1.0f + erff(o11 * 0.70710678118654752f));
            } else if (EPI == 2) {
                const float* rp0 = res + (size_t)r0 * N + c;
                const float* rp1 = res + (size_t)(r0 + 8) * N + c;
                o00 += rp0[0]; o01 += rp0[1];
                o10 += rp1[0]; o11 += rp1[1];
            }
            if (EPI == 2) {
                *(float2*)((float*)C + (size_t)r0 * N + c)       = make_float2(o00, o01);
                *(float2*)((float*)C + (size_t)(r0 + 8) * N + c) = make_float2(o10, o11);
            } else {
                __half2 v0 = __floats2half2_rn(o00, o01);
                __half2 v1 = __floats2half2_rn(o10, o11);
                *(uint32_t*)((__half*)C + (size_t)r0 * N + c)       = *(uint32_t*)&v0;
                *(uint32_t*)((__half*)C + (size_t)(r0 + 8) * N + c) = *(uint32_t*)&v1;
            }
        }
    }
}

// ---------------- attention: fp16 mma.sync flash-style (register-P) ---------
// block = (b,h) x 128 q-rows; 256 threads = 8 warps x 16 q-rows.
// K/V 64-token tiles double-buffered; P stays in registers (S C-frag == P A-frag).
#define APAD 72
#define KS_H (64*APAD)          // halves
#define VS_H (64*APAD)
#define KS_B (KS_H*2)
#define VS_B (VS_H*2)
#define ATT_SMEM ((2*KS_H + 2*VS_H)*2 + 2*64*4)   // 37376 B

__global__ __launch_bounds__(256, 2)
void attn_mma(const __half* __restrict__ QKV, const int* __restrict__ mask,
              __half* __restrict__ O)
{
    extern __shared__ __half sm[];
    __half* Ks = sm;
    __half* Vs = sm + 2 * KS_H;
    int*    Ms = (int*)(Vs + 2 * VS_H);

    const int tid = threadIdx.x, lane = tid & 31, w = tid >> 5;
    const int gid = lane >> 2, tig = lane & 3;
    const int b = blockIdx.y >> 4, h = blockIdx.y & 15;
    const int q0 = blockIdx.x * 128, m0 = w * 16;
    const size_t tokbase = (size_t)b * SEQ;
    const int qoff = h * DK, koff = DMODEL + h * DK, voff = 2 * DMODEL + h * DK;
    const int rlo = (lane & 7) + ((lane >> 3) & 1) * 8;
    const int khi = (lane >> 4) * 8;

    const uint32_t ksb = smem_u32(Ks), vsb = smem_u32(Vs), msb = smem_u32(Ms);

    // ---- stage Q (scaled by 1/8) into Ks(rows 0-63)/Vs(rows 64-127) --------
    const __half2 qscale = __floats2half2_rn(0.125f, 0.125f);
#pragma unroll
    for (int it = 0; it < 4; it++) {
        int idx = tid + it * 256;             // 0..1023 chunks of 8 halves
        int r = idx >> 3, j = (idx & 7) * 8;
        uint4 t = *(const uint4*)(QKV + (tokbase + q0 + r) * QKV_STR + qoff + j);
        __half2* hp = (__half2*)&t;
#pragma unroll
        for (int e = 0; e < 4; e++) hp[e] = __hmul2(hp[e], qscale);
        __half* dst = (r < 64) ? (Ks + r * APAD + j) : (Vs + (r - 64) * APAD + j);
        *(uint4*)dst = t;
    }
    __syncthreads();
    uint32_t qf[4][4];
    {
        const uint32_t qbase = (m0 < 64) ? ksb : vsb;
        const int qrow = (m0 < 64) ? m0 : m0 - 64;
#pragma unroll
        for (int ks = 0; ks < 4; ks++)
            ldmx4(qf[ks], qbase + (uint32_t)(((qrow + rlo) * APAD + ks * 16 + khi) * 2));
    }
    __syncthreads();

    float o[8][4];
#pragma unroll
    for (int a = 0; a < 8; a++)
#pragma unroll
        for (int e = 0; e < 4; e++) o[a][e] = 0.f;
    float l0 = 0.f, l1 = 0.f;

    // prologue: load tile 0 into buf 0
    {
#pragma unroll
        for (int it = 0; it < 2; it++) {
            int idx = tid + it * 256;        // 0..511
            int r = idx >> 3, j = (idx & 7) * 8;
            const __half* src = QKV + (tokbase + r) * QKV_STR;
            cp_async16(ksb + (uint32_t)((r * APAD + j) * 2), src + koff + j);
            cp_async16(vsb + (uint32_t)((r * APAD + j) * 2), src + voff + j);
        }
        if (tid < 16) cp_async16(msb + tid * 16, mask + b * SEQ + tid * 4);
        asm volatile("cp.async.commit_group;" ::: "memory");
    }

    const int NT = SEQ / 64;
    for (int kt = 0; kt < NT; kt++) {
        const int buf = kt & 1;
        if (kt + 1 < NT) {
            const int nb = buf ^ 1;
            const int t0 = (kt + 1) * 64;
#pragma unroll
            for (int it = 0; it < 2; it++) {
                int idx = tid + it * 256;
                int r = idx >> 3, j = (idx & 7) * 8;
                const __half* src = QKV + (tokbase + t0 + r) * QKV_STR;
                cp_async16(ksb + (uint32_t)((nb * KS_H + r * APAD + j) * 2), src + koff + j);
                cp_async16(vsb + (uint32_t)((nb * VS_H + r * APAD + j) * 2), src + voff + j);
            }
            if (tid < 16) cp_async16(msb + nb * 256 + tid * 16, mask + b * SEQ + t0 + tid * 4);
            asm volatile("cp.async.commit_group;" ::: "memory");
            asm volatile("cp.async.wait_group 1;" ::: "memory");
        } else {
            asm volatile("cp.async.wait_group 0;" ::: "memory");
        }
        __syncthreads();

        const uint32_t kb_ = ksb + (uint32_t)(buf * KS_B);
        const uint32_t vb_ = vsb + (uint32_t)(buf * VS_B);
        const int*     ms_ = Ms + buf * 64;

#pragma unroll
        for (int atp = 0; atp < 4; atp++) {
            const int n0 = atp * 16;
            float s0[4] = {0.f, 0.f, 0.f, 0.f};
            float s1[4] = {0.f, 0.f, 0.f, 0.f};
#pragma unroll
            for (int ks = 0; ks < 4; ks++) {
                uint32_t kf[4];
                ldmx4(kf, kb_ + (uint32_t)(((n0 + rlo) * APAD + ks * 16 + khi) * 2));
                uint32_t b0[2] = {kf[0], kf[2]};
                uint32_t b1[2] = {kf[1], kf[3]};
                mma_f16(s0, qf[ks], b0);
                mma_f16(s1, qf[ks], b1);
            }
            const int c0 = n0 + 2 * tig;
            const int mk0 = ms_[c0],     mk1 = ms_[c0 + 1];
            const int mk2 = ms_[c0 + 8], mk3 = ms_[c0 + 9];
            float p00 = mk0 ? __expf(s0[0]) : 0.f;
            float p01 = mk1 ? __expf(s0[1]) : 0.f;
            float p02 = mk0 ? __expf(s0[2]) : 0.f;
            float p03 = mk1 ? __expf(s0[3]) : 0.f;
            float p10 = mk2 ? __expf(s1[0]) : 0.f;
            float p11 = mk3 ? __expf(s1[1]) : 0.f;
            float p12 = mk2 ? __expf(s1[2]) : 0.f;
            float p13 = mk3 ? __expf(s1[3]) : 0.f;
            l0 += p00 + p01 + p10 + p11;
            l1 += p02 + p03 + p12 + p13;
            uint32_t af[4];
            __half2 t;
            t = __floats2half2_rn(p00, p01); af[0] = *(uint32_t*)&t;
            t = __floats2half2_rn(p02, p03); af[1] = *(uint32_t*)&t;
            t = __floats2half2_rn(p10, p11); af[2] = *(uint32_t*)&t;
            t = __floats2half2_rn(p12, p13); af[3] = *(uint32_t*)&t;
#pragma unroll
            for (int dp = 0; dp < 4; dp++) {
                uint32_t vf[4];
                ldmx4t(vf, vb_ + (uint32_t)(((n0 + rlo) * APAD + dp * 16 + khi) * 2));
                uint32_t b0[2] = {vf[0], vf[1]};
                uint32_t b1[2] = {vf[2], vf[3]};
                mma_f16(o[2 * dp],     af, b0);
                mma_f16(o[2 * dp + 1], af, b1);
            }
        }
        __syncthreads();   // all warps done with this buf before it is reloaded
    }

    // row sums across quad
    l0 += __shfl_xor_sync(0xffffffffu, l0, 1);
    l0 += __shfl_xor_sync(0xffffffffu, l0, 2);
    l1 += __shfl_xor_sync(0xffffffffu, l1, 1);
    l1 += __shfl_xor_sync(0xffffffffu, l1, 2);
    const float inv0 = 1.0f / l0, inv1 = 1.0f / l1;

    __half* o0 = O + (tokbase + q0 + m0 + gid)     * DMODEL + h * DK;
    __half* o1 = O + (tokbase + q0 + m0 + gid + 8) * DMODEL + h * DK;
#pragma unroll
    for (int at = 0; at < 8; at++) {
        const int c = at * 8 + 2 * tig;
        __half2 v0 = __floats2half2_rn(o[at][0] * inv0, o[at][1] * inv0);
        __half2 v1 = __floats2half2_rn(o[at][2] * inv1, o[at][3] * inv1);
        *(uint32_t*)(o0 + c) = *(uint32_t*)&v0;
        *(uint32_t*)(o1 + c) = *(uint32_t*)&v1;
    }
}

// ---------------- launcher ---------------------------------------------------
extern "C" void kernel_launch(void* const* d_in, const int* in_sizes, int n_in,
                              void* d_out, int out_size)
{
    const float* x     = (const float*)d_in[0];
    const int*   mask  = (const int*)  d_in[1];
    const float* Wq    = (const float*)d_in[2];
    const float* bq    = (const float*)d_in[3];
    const float* Wk    = (const float*)d_in[4];
    const float* bk    = (const float*)d_in[5];
    const float* Wv    = (const float*)d_in[6];
    const float* bv    = (const float*)d_in[7];
    const float* Wo    = (const float*)d_in[8];
    const float* bo    = (const float*)d_in[9];
    const float* W1    = (const float*)d_in[10];
    const float* b1    = (const float*)d_in[11];
    const float* W2    = (const float*)d_in[12];
    const float* b2    = (const float*)d_in[13];
    const float* ln1g  = (const float*)d_in[14];
    const float* ln1b  = (const float*)d_in[15];
    const float* ln2g  = (const float*)d_in[16];
    const float* ln2b  = (const float*)d_in[17];
    float* out = (float*)d_out;

    __half *h, *qkv, *att, *h2, *ff1, *wqkvt, *wot, *w1t, *w2t;
    float *x1, *bqkv;
    cudaGetSymbolAddress((void**)&h,    g_h);
    cudaGetSymbolAddress((void**)&qkv,  g_qkv);
    cudaGetSymbolAddress((void**)&att,  g_att);
    cudaGetSymbolAddress((void**)&x1,   g_x1);
    cudaGetSymbolAddress((void**)&h2,   g_h2);
    cudaGetSymbolAddress((void**)&ff1,  g_ff1);
    cudaGetSymbolAddress((void**)&wqkvt,g_wqkvt);
    cudaGetSymbolAddress((void**)&bqkv, g_bqkv);
    cudaGetSymbolAddress((void**)&wot,  g_wot);
    cudaGetSymbolAddress((void**)&w1t,  g_w1t);
    cudaGetSymbolAddress((void**)&w2t,  g_w2t);

    const int SMEM_GEMM = 4 * GSTAGE_H * 2;   // 73728 B
    cudaFuncSetAttribute((gemm_mma<0, __half>), cudaFuncAttributeMaxDynamicSharedMemorySize, SMEM_GEMM);
    cudaFuncSetAttribute((gemm_mma<1, __half>), cudaFuncAttributeMaxDynamicSharedMemorySize, SMEM_GEMM);
    cudaFuncSetAttribute((gemm_mma<2, float>),  cudaFuncAttributeMaxDynamicSharedMemorySize, SMEM_GEMM);
    cudaFuncSetAttribute(attn_mma, cudaFuncAttributeMaxDynamicSharedMemorySize, ATT_SMEM);

    dim3 tpb(32, 8);
    tp_h<<<dim3(DMODEL/32, DMODEL/32), tpb>>>(Wq, wqkvt,                   DMODEL, DMODEL);
    tp_h<<<dim3(DMODEL/32, DMODEL/32), tpb>>>(Wk, wqkvt + DMODEL*DMODEL,   DMODEL, DMODEL);
    tp_h<<<dim3(DMODEL/32, DMODEL/32), tpb>>>(Wv, wqkvt + 2*DMODEL*DMODEL, DMODEL, DMODEL);
    tp_h<<<dim3(DMODEL/32, DMODEL/32), tpb>>>(Wo, wot, DMODEL, DMODEL);
    tp_h<<<dim3(DFF/32,    DMODEL/32), tpb>>>(W1, w1t, DMODEL, DFF);
    tp_h<<<dim3(DMODEL/32, DFF/32),    tpb>>>(W2, w2t, DFF, DMODEL);
    bias_cat<<<QKV_STR/256, 256>>>(bq, bk, bv, bqkv);

    dim3 gD(DMODEL / 128, NTOK / 128);   // (8, 64)
    dim3 gQKV(QKV_STR / 128, NTOK / 128);// (24, 64)
    dim3 gF(DFF / 128,    NTOK / 128);   // (32, 64)

    // h = LN1(x) -> fp16
    ln_kernel<<<NTOK, 256>>>(x, ln1g, ln1b, h);
    // fused QKV projection -> fp16
    gemm_mma<0, __half><<<gQKV, 256, SMEM_GEMM>>>(h, wqkvt, bqkv, nullptr, qkv, NTOK, QKV_STR, DMODEL);
    // attention -> fp16
    attn_mma<<<dim3(SEQ / 128, BATCH * NHEADS), 256, ATT_SMEM>>>(qkv, mask, att);
    // x1 = x + att @ Wo + bo  (fp32)
    gemm_mma<2, float><<<gD, 256, SMEM_GEMM>>>(att, wot, bo, x, x1, NTOK, DMODEL, DMODEL);
    // h2 = LN2(x1) -> fp16
    ln_kernel<<<NTOK, 256>>>(x1, ln2g, ln2b, h2);
    // ff1 = gelu(h2 @ W1 + b1) -> fp16
    gemm_mma<1, __half><<<gF, 256, SMEM_GEMM>>>(h2, w1t, b1, nullptr, ff1, NTOK, DFF, DMODEL);
    // out = x1 + ff1 @ W2 + b2  (fp32)
    gemm_mma<2, float><<<gD, 256, SMEM_GEMM>>>(ff1, w2t, b2, x1, out, NTOK, DMODEL, DFF);
}

// round 10
// speedup vs baseline: 1.6036x; 1.0155x over previous
#include <cuda_runtime.h>
#include <cuda_fp16.h>
#include <math.h>
#include <stdint.h>

#define BATCH 4
#define SEQ   2048
#define DMODEL 1024
#define NHEADS 16
#define DK    64
#define DFF   4096
#define NTOK  (BATCH*SEQ)          // 8192
#define QKV_STR 3072
#define QSCALE 0.18033688011112042f   // log2(e)/8, baked into Wq/bq

// ---------------- scratch (device globals; no allocation allowed) ----------
__device__ __half g_h   [NTOK*DMODEL];
__device__ __half g_qkv [NTOK*QKV_STR];
__device__ __half g_att [NTOK*DMODEL];
__device__ float  g_x1  [NTOK*DMODEL];
__device__ __half g_h2  [NTOK*DMODEL];
__device__ __half g_ff1 [NTOK*DFF];
// transposed (K-major, fp16) weights
__device__ __half g_wqkvt[3*DMODEL*DMODEL];  // [N=3072, K=1024]
__device__ float  g_bqkv [QKV_STR];
__device__ __half g_wot[DMODEL*DMODEL];
__device__ __half g_w1t[DFF*DMODEL];
__device__ __half g_w2t[DMODEL*DFF];

// ---------------- helpers ----------------------------------------------------
__device__ __forceinline__ uint32_t smem_u32(const void* p) {
    uint32_t a;
    asm("{ .reg .u64 t; cvta.to.shared.u64 t, %1; cvt.u32.u64 %0, t; }"
        : "=r"(a) : "l"(p));
    return a;
}
__device__ __forceinline__ void cp_async16(uint32_t dst, const void* src) {
    asm volatile("cp.async.cg.shared.global [%0], [%1], 16;" :: "r"(dst), "l"(src));
}
__device__ __forceinline__ float ex2f(float x) {
    float r;
    asm("ex2.approx.f32 %0, %1;" : "=f"(r) : "f"(x));
    return r;
}

__device__ __forceinline__ void mma_f16(float (&d)[4], const uint32_t (&a)[4],
                                        const uint32_t (&b)[2]) {
    asm volatile("mma.sync.aligned.m16n8k16.row.col.f32.f16.f16.f32 "
        "{%0,%1,%2,%3}, {%4,%5,%6,%7}, {%8,%9}, {%0,%1,%2,%3};"
        : "+f"(d[0]), "+f"(d[1]), "+f"(d[2]), "+f"(d[3])
        : "r"(a[0]), "r"(a[1]), "r"(a[2]), "r"(a[3]), "r"(b[0]), "r"(b[1]));
}
__device__ __forceinline__ void ldmx4(uint32_t (&r)[4], uint32_t addr) {
    asm volatile("ldmatrix.sync.aligned.m8n8.x4.shared.b16 {%0,%1,%2,%3}, [%4];"
        : "=r"(r[0]), "=r"(r[1]), "=r"(r[2]), "=r"(r[3]) : "r"(addr));
}
__device__ __forceinline__ void ldmx4t(uint32_t (&r)[4], uint32_t addr) {
    asm volatile("ldmatrix.sync.aligned.m8n8.x4.trans.shared.b16 "
        "{%0,%1,%2,%3}, [%4];"
        : "=r"(r[0]), "=r"(r[1]), "=r"(r[2]), "=r"(r[3]) : "r"(addr));
}

// ---------------- layernorm: one block per token row -> fp16 out ------------
__global__ __launch_bounds__(256) void ln_kernel(const float* __restrict__ x,
                                                 const float* __restrict__ g,
                                                 const float* __restrict__ b,
                                                 __half* __restrict__ y)
{
    const int row = blockIdx.x;
    const int tid = threadIdx.x;
    const float* xr = x + (size_t)row * DMODEL;
    float4 v = *(const float4*)(xr + tid * 4);
    float s  = v.x + v.y + v.z + v.w;
    float s2 = v.x*v.x + v.y*v.y + v.z*v.z + v.w*v.w;

    __shared__ float red[64], red2[64];
    for (int o = 16; o > 0; o >>= 1) {
        s  += __shfl_xor_sync(0xffffffffu, s,  o);
        s2 += __shfl_xor_sync(0xffffffffu, s2, o);
    }
    int wid = tid >> 5, lid = tid & 31;
    if (lid == 0) { red[wid] = s; red2[wid] = s2; }
    __syncthreads();
    if (wid == 0) {
        float a  = (lid < 8) ? red[lid]  : 0.f;
        float a2 = (lid < 8) ? red2[lid] : 0.f;
        for (int o = 4; o > 0; o >>= 1) {
            a  += __shfl_xor_sync(0xffffffffu, a,  o);
            a2 += __shfl_xor_sync(0xffffffffu, a2, o);
        }
        if (lid == 0) { red[0] = a; red2[0] = a2; }
    }
    __syncthreads();
    float mu  = red[0]  * (1.0f / DMODEL);
    float var = red2[0] * (1.0f / DMODEL) - mu * mu;
    float rstd = rsqrtf(var + 1e-5f);

    int c = tid * 4;
    float4 gg = *(const float4*)(g + c);
    float4 bb = *(const float4*)(b + c);
    __half2 h01 = __floats2half2_rn((v.x - mu) * rstd * gg.x + bb.x,
                                    (v.y - mu) * rstd * gg.y + bb.y);
    __half2 h23 = __floats2half2_rn((v.z - mu) * rstd * gg.z + bb.z,
                                    (v.w - mu) * rstd * gg.w + bb.w);
    uint2 u;
    u.x = *(uint32_t*)&h01; u.y = *(uint32_t*)&h23;
    *(uint2*)(y + (size_t)row * DMODEL + c) = u;
}

// ---------------- fused weight transpose -> fp16 (all 6 weights) ------------
struct TpSegs {
    const float* W[6];
    __half*      Wt[6];
    int          K[6], N[6];
    int          tstart[7];
    float        scale[6];
};

__global__ __launch_bounds__(256) void tp_fused(TpSegs segs)
{
    __shared__ float t[32][33];
    const int bid = blockIdx.x;
    int s = 0;
#pragma unroll
    for (int i = 1; i < 6; i++) if (bid >= segs.tstart[i]) s = i;
    const int ti = bid - segs.tstart[s];
    const int K = segs.K[s], N = segs.N[s];
    const int ntn = N >> 5;
    const int n0 = (ti % ntn) * 32, k0 = (ti / ntn) * 32;
    const float* W  = segs.W[s];
    __half*      Wt = segs.Wt[s];
    const float  sc = segs.scale[s];
    const int tx = threadIdx.x, ty = threadIdx.y;   // 32 x 8
#pragma unroll
    for (int i = 0; i < 4; i++)
        t[ty + i*8][tx] = W[(size_t)(k0 + ty + i*8) * N + n0 + tx];
    __syncthreads();
#pragma unroll
    for (int i = 0; i < 4; i++)
        Wt[(size_t)(n0 + ty + i*8) * K + k0 + tx] =
            __float2half_rn(t[tx][ty + i*8] * sc);
}

__global__ void bias_cat(const float* bq, const float* bk, const float* bv,
                         float* o)
{
    int i = blockIdx.x * 256 + threadIdx.x;
    o[i] = (i < DMODEL) ? bq[i] * QSCALE
         : (i < 2*DMODEL) ? bk[i - DMODEL] : bv[i - 2*DMODEL];
}

// ---------------- fp16 mma.sync GEMM: 3-stage cp.async, 1 sync per tile -----
// 128x128 tile, BK=64, 256 threads (8 warps, warp tile 64x32).
// EPI: 0 = bias -> half, 1 = bias+gelu -> half, 2 = bias+residual -> float
#define GST 72
#define GSTG (128*GST)         // halves per stage per operand (9216)
#define SMEM_GEMM (6*GSTG*2)   // 110592 B

template<int EPI, typename TC>
__global__ __launch_bounds__(256, 2)
void gemm_mma(const __half* __restrict__ A, const __half* __restrict__ Bt,
              const float* __restrict__ bias, const float* __restrict__ res,
              TC* __restrict__ C, int M, int N, int K)
{
    extern __shared__ __half smh[];
    __half* As = smh;                    // [3][128][GST]
    __half* Bs = smh + 3 * GSTG;
    const int tid = threadIdx.x, lane = tid & 31, w = tid >> 5;
    const int wm = w & 1, wn = w >> 1;
    const int gid = lane >> 2, tig = lane & 3;
    const int row0 = blockIdx.y * 128, col0 = blockIdx.x * 128;

    const uint32_t asb = smem_u32(As), bsb = smem_u32(Bs);

    auto load_stage = [&](int st, int kof) {
#pragma unroll
        for (int it = 0; it < 4; it++) {
            int idx = tid + it * 256;      // 0..1023
            int r = idx >> 3, j = idx & 7;
            uint32_t d = (uint32_t)((st * GSTG + r * GST + j * 8) * 2);
            cp_async16(asb + d, A  + (size_t)(row0 + r) * K + kof + j * 8);
            cp_async16(bsb + d, Bt + (size_t)(col0 + r) * K + kof + j * 8);
        }
        asm volatile("cp.async.commit_group;" ::: "memory");
    };

    float acc[4][4][4];
#pragma unroll
    for (int i = 0; i < 4; i++)
#pragma unroll
        for (int j = 0; j < 4; j++)
#pragma unroll
            for (int e = 0; e < 4; e++) acc[i][j][e] = 0.f;

    const int NCH = K >> 6;    // >= 16 always
    load_stage(0, 0);
    load_stage(1, 64);

    for (int i = 0; i < NCH; i++) {
        if (i + 1 < NCH) asm volatile("cp.async.wait_group 1;" ::: "memory");
        else             asm volatile("cp.async.wait_group 0;" ::: "memory");
        __syncthreads();
        if (i + 2 < NCH) load_stage((i + 2) % 3, (i + 2) << 6);

        const __half* as = As + (i % 3) * GSTG;
        const __half* bs = Bs + (i % 3) * GSTG;
#pragma unroll
        for (int ks = 0; ks < 4; ks++) {
            const int k0 = ks * 16 + 2 * tig;
            uint32_t af[4][4], bf[4][2];
#pragma unroll
            for (int mt = 0; mt < 4; mt++) {
                int r = wm * 64 + mt * 16 + gid;
                af[mt][0] = *(const uint32_t*)&as[r * GST + k0];
                af[mt][1] = *(const uint32_t*)&as[(r + 8) * GST + k0];
                af[mt][2] = *(const uint32_t*)&as[r * GST + k0 + 8];
                af[mt][3] = *(const uint32_t*)&as[(r + 8) * GST + k0 + 8];
            }
#pragma unroll
            for (int nt = 0; nt < 4; nt++) {
                int n = wn * 32 + nt * 8 + gid;
                bf[nt][0] = *(const uint32_t*)&bs[n * GST + k0];
                bf[nt][1] = *(const uint32_t*)&bs[n * GST + k0 + 8];
            }
#pragma unroll
            for (int mt = 0; mt < 4; mt++)
#pragma unroll
                for (int nt = 0; nt < 4; nt++)
                    mma_f16(acc[mt][nt], af[mt], bf[nt]);
        }
    }

#pragma unroll
    for (int mt = 0; mt < 4; mt++) {
        const int r0 = row0 + wm * 64 + mt * 16 + gid;
#pragma unroll
        for (int nt = 0; nt < 4; nt++) {
            const int c = col0 + wn * 32 + nt * 8 + 2 * tig;
            const float b0 = bias[c], b1 = bias[c + 1];
            float o00 = acc[mt][nt][0] + b0, o01 = acc[mt][nt][1] + b1;
            float o10 = acc[mt][nt][2] + b0, o11 = acc[mt][nt][3] + b1;
            if (EPI == 1) {
                o00 = 0.5f * o00 * (1.0f + erff(o00 * 0.70710678118654752f));
                o01 = 0.5f * o01 * (1.0f + erff(o01 * 0.70710678118654752f));
                o10 = 0.5f * o10 * (1.0f + erff(o10 * 0.70710678118654752f));
                o11 = 0.5f * o11 * (1.0f + erff(o11 * 0.70710678118654752f));
            } else if (EPI == 2) {
                const float* rp0 = res + (size_t)r0 * N + c;
                const float* rp1 = res + (size_t)(r0 + 8) * N + c;
                o00 += rp0[0]; o01 += rp0[1];
                o10 += rp1[0]; o11 += rp1[1];
            }
            if (EPI == 2) {
                *(float2*)((float*)C + (size_t)r0 * N + c)       = make_float2(o00, o01);
                *(float2*)((float*)C + (size_t)(r0 + 8) * N + c) = make_float2(o10, o11);
            } else {
                __half2 v0 = __floats2half2_rn(o00, o01);
                __half2 v1 = __floats2half2_rn(o10, o11);
                *(uint32_t*)((__half*)C + (size_t)r0 * N + c)       = *(uint32_t*)&v0;
                *(uint32_t*)((__half*)C + (size_t)(r0 + 8) * N + c) = *(uint32_t*)&v1;
            }
        }
    }
}

// ---------------- attention: fp16 mma, 3-stage pipeline, base-2 softmax -----
// block = (b,h) x 128 q-rows; 256 threads = 8 warps x 16 q-rows.
// Scores already in log2 units (scale baked into Wq/bq) -> raw ex2.
#define APAD 72
#define KSTG (64*APAD)          // halves per stage (4608)
#define ATT_SMEM (6*KSTG*2 + 3*64*4)   // 56064 B

__global__ __launch_bounds__(256, 2)
void attn_mma(const __half* __restrict__ QKV, const int* __restrict__ mask,
              __half* __restrict__ O)
{
    extern __shared__ __half sm[];
    __half* Ks = sm;                   // [3][64][APAD]
    __half* Vs = sm + 3 * KSTG;        // [3][64][APAD]
    int*    Ms = (int*)(Vs + 3 * KSTG);

    const int tid = threadIdx.x, lane = tid & 31, w = tid >> 5;
    const int gid = lane >> 2, tig = lane & 3;
    const int b = blockIdx.y >> 4, h = blockIdx.y & 15;
    const int q0 = blockIdx.x * 128, m0 = w * 16;
    const size_t tokbase = (size_t)b * SEQ;
    const int qoff = h * DK, koff = DMODEL + h * DK, voff = 2 * DMODEL + h * DK;
    const int rlo = (lane & 7) + ((lane >> 3) & 1) * 8;
    const int khi = (lane >> 4) * 8;

    const uint32_t ksb = smem_u32(Ks), vsb = smem_u32(Vs), msb = smem_u32(Ms);

    // ---- stage Q (scale pre-baked into Wq/bq) into Ks/Vs stage 0 -----------
#pragma unroll
    for (int it = 0; it < 4; it++) {
        int idx = tid + it * 256;             // 0..1023 chunks of 8 halves
        int r = idx >> 3, j = (idx & 7) * 8;
        uint4 t = *(const uint4*)(QKV + (tokbase + q0 + r) * QKV_STR + qoff + j);
        __half* dst = (r < 64) ? (Ks + r * APAD + j) : (Vs + (r - 64) * APAD + j);
        *(uint4*)dst = t;
    }
    __syncthreads();
    uint32_t qf[4][4];
    {
        const uint32_t qbase = (m0 < 64) ? ksb : vsb;
        const int qrow = (m0 < 64) ? m0 : m0 - 64;
#pragma unroll
        for (int ks = 0; ks < 4; ks++)
            ldmx4(qf[ks], qbase + (uint32_t)(((qrow + rlo) * APAD + ks * 16 + khi) * 2));
    }
    __syncthreads();

    auto load_tile = [&](int st, int t0) {
#pragma unroll
        for (int it = 0; it < 2; it++) {
            int idx = tid + it * 256;        // 0..511
            int r = idx >> 3, j = (idx & 7) * 8;
            const __half* src = QKV + (tokbase + t0 + r) * QKV_STR;
            cp_async16(ksb + (uint32_t)((st * KSTG + r * APAD + j) * 2), src + koff + j);
            cp_async16(vsb + (uint32_t)((st * KSTG + r * APAD + j) * 2), src + voff + j);
        }
        if (tid < 16) cp_async16(msb + st * 256 + tid * 16, mask + b * SEQ + t0 + tid * 4);
        asm volatile("cp.async.commit_group;" ::: "memory");
    };

    float o[8][4];
#pragma unroll
    for (int a = 0; a < 8; a++)
#pragma unroll
        for (int e = 0; e < 4; e++) o[a][e] = 0.f;
    float l0 = 0.f, l1 = 0.f;

    const int NT = SEQ / 64;   // 32
    load_tile(0, 0);
    load_tile(1, 64);

    for (int kt = 0; kt < NT; kt++) {
        if (kt + 1 < NT) asm volatile("cp.async.wait_group 1;" ::: "memory");
        else             asm volatile("cp.async.wait_group 0;" ::: "memory");
        __syncthreads();
        if (kt + 2 < NT) load_tile((kt + 2) % 3, (kt + 2) * 64);

        const int st = kt % 3;
        const uint32_t kb_ = ksb + (uint32_t)(st * KSTG * 2);
        const uint32_t vb_ = vsb + (uint32_t)(st * KSTG * 2);
        const int*     ms_ = Ms + st * 64;

#pragma unroll
        for (int atp = 0; atp < 4; atp++) {
            const int n0 = atp * 16;
            float s0[4] = {0.f, 0.f, 0.f, 0.f};
            float s1[4] = {0.f, 0.f, 0.f, 0.f};
#pragma unroll
            for (int ks = 0; ks < 4; ks++) {
                uint32_t kf[4];
                ldmx4(kf, kb_ + (uint32_t)(((n0 + rlo) * APAD + ks * 16 + khi) * 2));
                uint32_t b0[2] = {kf[0], kf[2]};
                uint32_t b1[2] = {kf[1], kf[3]};
                mma_f16(s0, qf[ks], b0);
                mma_f16(s1, qf[ks], b1);
            }
            const int c0 = n0 + 2 * tig;
            const int mk0 = ms_[c0],     mk1 = ms_[c0 + 1];
            const int mk2 = ms_[c0 + 8], mk3 = ms_[c0 + 9];
            float p00 = mk0 ? ex2f(s0[0]) : 0.f;
            float p01 = mk1 ? ex2f(s0[1]) : 0.f;
            float p02 = mk0 ? ex2f(s0[2]) : 0.f;
            float p03 = mk1 ? ex2f(s0[3]) : 0.f;
            float p10 = mk2 ? ex2f(s1[0]) : 0.f;
            float p11 = mk3 ? ex2f(s1[1]) : 0.f;
            float p12 = mk2 ? ex2f(s1[2]) : 0.f;
            float p13 = mk3 ? ex2f(s1[3]) : 0.f;
            l0 += p00 + p01 + p10 + p11;
            l1 += p02 + p03 + p12 + p13;
            uint32_t af[4];
            __half2 t;
            t = __floats2half2_rn(p00, p01); af[0] = *(uint32_t*)&t;
            t = __floats2half2_rn(p02, p03); af[1] = *(uint32_t*)&t;
            t = __floats2half2_rn(p10, p11); af[2] = *(uint32_t*)&t;
            t = __floats2half2_rn(p12, p13); af[3] = *(uint32_t*)&t;
#pragma unroll
            for (int dp = 0; dp < 4; dp++) {
                uint32_t vf[4];
                ldmx4t(vf, vb_ + (uint32_t)(((n0 + rlo) * APAD + dp * 16 + khi) * 2));
                uint32_t b0[2] = {vf[0], vf[1]};
                uint32_t b1[2] = {vf[2], vf[3]};
                mma_f16(o[2 * dp],     af, b0);
                mma_f16(o[2 * dp + 1], af, b1);
            }
        }
    }

    // row sums across quad
    l0 += __shfl_xor_sync(0xffffffffu, l0, 1);
    l0 += __shfl_xor_sync(0xffffffffu, l0, 2);
    l1 += __shfl_xor_sync(0xffffffffu, l1, 1);
    l1 += __shfl_xor_sync(0xffffffffu, l1, 2);
    const float inv0 = 1.0f / l0, inv1 = 1.0f / l1;

    __half* o0 = O + (tokbase + q0 + m0 + gid)     * DMODEL + h * DK;
    __half* o1 = O + (tokbase + q0 + m0 + gid + 8) * DMODEL + h * DK;
#pragma unroll
    for (int at = 0; at < 8; at++) {
        const int c = at * 8 + 2 * tig;
        __half2 v0 = __floats2half2_rn(o[at][0] * inv0, o[at][1] * inv0);
        __half2 v1 = __floats2half2_rn(o[at][2] * inv1, o[at][3] * inv1);
        *(uint32_t*)(o0 + c) = *(uint32_t*)&v0;
        *(uint32_t*)(o1 + c) = *(uint32_t*)&v1;
    }
}

// ---------------- launcher ---------------------------------------------------
extern "C" void kernel_launch(void* const* d_in, const int* in_sizes, int n_in,
                              void* d_out, int out_size)
{
    const float* x     = (const float*)d_in[0];
    const int*   mask  = (const int*)  d_in[1];
    const float* Wq    = (const float*)d_in[2];
    const float* bq    = (const float*)d_in[3];
    const float* Wk    = (const float*)d_in[4];
    const float* bk    = (const float*)d_in[5];
    const float* Wv    = (const float*)d_in[6];
    const float* bv    = (const float*)d_in[7];
    const float* Wo    = (const float*)d_in[8];
    const float* bo    = (const float*)d_in[9];
    const float* W1    = (const float*)d_in[10];
    const float* b1    = (const float*)d_in[11];
    const float* W2    = (const float*)d_in[12];
    const float* b2    = (const float*)d_in[13];
    const float* ln1g  = (const float*)d_in[14];
    const float* ln1b  = (const float*)d_in[15];
    const float* ln2g  = (const float*)d_in[16];
    const float* ln2b  = (const float*)d_in[17];
    float* out = (float*)d_out;

    __half *h, *qkv, *att, *h2, *ff1, *wqkvt, *wot, *w1t, *w2t;
    float *x1, *bqkv;
    cudaGetSymbolAddress((void**)&h,    g_h);
    cudaGetSymbolAddress((void**)&qkv,  g_qkv);
    cudaGetSymbolAddress((void**)&att,  g_att);
    cudaGetSymbolAddress((void**)&x1,   g_x1);
    cudaGetSymbolAddress((void**)&h2,   g_h2);
    cudaGetSymbolAddress((void**)&ff1,  g_ff1);
    cudaGetSymbolAddress((void**)&wqkvt,g_wqkvt);
    cudaGetSymbolAddress((void**)&bqkv, g_bqkv);
    cudaGetSymbolAddress((void**)&wot,  g_wot);
    cudaGetSymbolAddress((void**)&w1t,  g_w1t);
    cudaGetSymbolAddress((void**)&w2t,  g_w2t);

    cudaFuncSetAttribute((gemm_mma<0, __half>), cudaFuncAttributeMaxDynamicSharedMemorySize, SMEM_GEMM);
    cudaFuncSetAttribute((gemm_mma<1, __half>), cudaFuncAttributeMaxDynamicSharedMemorySize, SMEM_GEMM);
    cudaFuncSetAttribute((gemm_mma<2, float>),  cudaFuncAttributeMaxDynamicSharedMemorySize, SMEM_GEMM);
    cudaFuncSetAttribute(attn_mma, cudaFuncAttributeMaxDynamicSharedMemorySize, ATT_SMEM);

    // fused weight prep: 6 transposes (+ fp16 round, + QSCALE on Wq)
    TpSegs segs;
    segs.W[0] = Wq; segs.Wt[0] = wqkvt;                   segs.K[0] = DMODEL; segs.N[0] = DMODEL; segs.scale[0] = QSCALE;
    segs.W[1] = Wk; segs.Wt[1] = wqkvt + DMODEL*DMODEL;   segs.K[1] = DMODEL; segs.N[1] = DMODEL; segs.scale[1] = 1.f;
    segs.W[2] = Wv; segs.Wt[2] = wqkvt + 2*DMODEL*DMODEL; segs.K[2] = DMODEL; segs.N[2] = DMODEL; segs.scale[2] = 1.f;
    segs.W[3] = Wo; segs.Wt[3] = wot;                     segs.K[3] = DMODEL; segs.N[3] = DMODEL; segs.scale[3] = 1.f;
    segs.W[4] = W1; segs.Wt[4] = w1t;                     segs.K[4] = DMODEL; segs.N[4] = DFF;    segs.scale[4] = 1.f;
    segs.W[5] = W2; segs.Wt[5] = w2t;                     segs.K[5] = DFF;    segs.N[5] = DMODEL; segs.scale[5] = 1.f;
    int tot = 0;
    for (int i = 0; i < 6; i++) {
        segs.tstart[i] = tot;
        tot += (segs.N[i] >> 5) * (segs.K[i] >> 5);
    }
    segs.tstart[6] = tot;   // 12288
    tp_fused<<<tot, dim3(32, 8)>>>(segs);
    bias_cat<<<QKV_STR/256, 256>>>(bq, bk, bv, bqkv);

    dim3 gD(DMODEL / 128, NTOK / 128);   // (8, 64)
    dim3 gQKV(QKV_STR / 128, NTOK / 128);// (24, 64)
    dim3 gF(DFF / 128,    NTOK / 128);   // (32, 64)

    // h = LN1(x) -> fp16
    ln_kernel<<<NTOK, 256>>>(x, ln1g, ln1b, h);
    // fused QKV projection -> fp16 (q pre-scaled by log2e/8 via weights)
    gemm_mma<0, __half><<<gQKV, 256, SMEM_GEMM>>>(h, wqkvt, bqkv, nullptr, qkv, NTOK, QKV_STR, DMODEL);
    // attention -> fp16
    attn_mma<<<dim3(SEQ / 128, BATCH * NHEADS), 256, ATT_SMEM>>>(qkv, mask, att);
    // x1 = x + att @ Wo + bo  (fp32)
    gemm_mma<2, float><<<gD, 256, SMEM_GEMM>>>(att, wot, bo, x, x1, NTOK, DMODEL, DMODEL);
    // h2 = LN2(x1) -> fp16
    ln_kernel<<<NTOK, 256>>>(x1, ln2g, ln2b, h2);
    // ff1 = gelu(h2 @ W1 + b1) -> fp16
    gemm_mma<1, __half><<<gF, 256, SMEM_GEMM>>>(h2, w1t, b1, nullptr, ff1, NTOK, DFF, DMODEL);
    // out = x1 + ff1 @ W2 + b2  (fp32)
    gemm_mma<2, float><<<gD, 256, SMEM_GEMM>>>(ff1, w2t, b2, x1, out, NTOK, DMODEL, DFF);
}